// round 15
// baseline (speedup 1.0000x reference)
#include <cuda_runtime.h>
#include <math.h>
#include <stdint.h>

#define S_DIM  384
#define CZ     128
#define H_DIM  4
#define CH     32
#define NROWS  (S_DIM*S_DIM)   // 147456

// ---------------- scratch (device globals; allocation-free) ----------------
// q/k/v are stored PRE-ROUNDED to tf32 (and q pre-scaled by 1/sqrt(CH)):
// attention staging is then a pure copy. Bit-identical to rounding in attn.
__device__ float g_q [(size_t)NROWS*CZ];   // tf32(q * scale)  (col = h*32+c)
__device__ float g_g [(size_t)NROWS*CZ];   // sigmoid gate (fp32)
__device__ float g_k [(size_t)NROWS*CH];   // tf32(k)
__device__ float g_v [(size_t)NROWS*CH];   // tf32(v)

// ---------------- helpers ----------------
__device__ __forceinline__ uint32_t f2tf32(float f) {
    uint32_t u; asm("cvt.rna.tf32.f32 %0, %1;" : "=r"(u) : "f"(f)); return u;
}
__device__ __forceinline__ uint4 f2tf32x4(float4 v) {
    return make_uint4(f2tf32(v.x), f2tf32(v.y), f2tf32(v.z), f2tf32(v.w));
}
__device__ __forceinline__ void mma_tf32(float* d, const uint32_t* a, const uint32_t* b) {
    asm volatile(
        "mma.sync.aligned.m16n8k8.row.col.f32.tf32.tf32.f32 "
        "{%0,%1,%2,%3}, {%4,%5,%6,%7}, {%8,%9}, {%0,%1,%2,%3};\n"
        : "+f"(d[0]), "+f"(d[1]), "+f"(d[2]), "+f"(d[3])
        : "r"(a[0]), "r"(a[1]), "r"(a[2]), "r"(a[3]), "r"(b[0]), "r"(b[1]));
}
// load 4 fp32 from smem (A fragment layout) and split into hi/lo tf32
__device__ __forceinline__ void load_split(const float* smf, int i0, int i1, int i2, int i3,
                                           uint32_t* ah, uint32_t* al) {
    float a0 = smf[i0], a1 = smf[i1], a2 = smf[i2], a3 = smf[i3];
    ah[0] = f2tf32(a0); al[0] = f2tf32(a0 - __uint_as_float(ah[0]));
    ah[1] = f2tf32(a1); al[1] = f2tf32(a1 - __uint_as_float(ah[1]));
    ah[2] = f2tf32(a2); al[2] = f2tf32(a2 - __uint_as_float(ah[2]));
    ah[3] = f2tf32(a3); al[3] = f2tf32(a3 - __uint_as_float(ah[3]));
}

// ---------------- kernel 1: LayerNorm + fused projections (single-pass tf32) ----------------
#define PA_STR 132
#define PB_STR 68
#define PROJ_SMEM (64*PA_STR*4 + 160*PB_STR*4)   // 77312 B
__global__ void __launch_bounds__(512, 2) proj_mma(const float* __restrict__ z,
                                                   const float* __restrict__ lnw,
                                                   const float* __restrict__ lnb,
                                                   const float* __restrict__ Wq,
                                                   const float* __restrict__ Wk,
                                                   const float* __restrict__ Wv,
                                                   const float* __restrict__ Wg,
                                                   const float* __restrict__ bg)
{
    extern __shared__ float sm[];
    uint32_t* Asu = reinterpret_cast<uint32_t*>(sm);                 // 64 x 132 tf32 (zn)
    uint32_t* Bsu = reinterpret_cast<uint32_t*>(sm + 64 * PA_STR);   // 160 x 68 tf32

    const int tid  = threadIdx.x;
    const int wid  = tid >> 5;
    const int lane = tid & 31;
    const int r = lane >> 2, c = lane & 3;
    const int wm = wid & 3, wn = wid >> 2;
    const int m0 = wm * 16, n0 = wn * 40;
    const int rowBase = blockIdx.x * 64;
    const float qscale = 0.17677669529663689f;  // 1/sqrt(32)

    // ---- fused LayerNorm -> tf32 zn in smem (once per CTA; STS.128 stores) ----
    {
        int row = tid >> 3;
        int sub = tid & 7;
        const float4* zr = reinterpret_cast<const float4*>(z + (size_t)(rowBase + row) * CZ) + sub * 4;
        float4 x0 = zr[0], x1 = zr[1], x2 = zr[2], x3 = zr[3];
        float s  = x0.x+x0.y+x0.z+x0.w + x1.x+x1.y+x1.z+x1.w
                 + x2.x+x2.y+x2.z+x2.w + x3.x+x3.y+x3.z+x3.w;
        float ss = x0.x*x0.x+x0.y*x0.y+x0.z*x0.z+x0.w*x0.w
                 + x1.x*x1.x+x1.y*x1.y+x1.z*x1.z+x1.w*x1.w
                 + x2.x*x2.x+x2.y*x2.y+x2.z*x2.z+x2.w*x2.w
                 + x3.x*x3.x+x3.y*x3.y+x3.z*x3.z+x3.w*x3.w;
        #pragma unroll
        for (int o = 1; o < 8; o <<= 1) {
            s  += __shfl_xor_sync(0xffffffffu, s,  o);
            ss += __shfl_xor_sync(0xffffffffu, ss, o);
        }
        float mean = s * (1.0f / CZ);
        float var  = ss * (1.0f / CZ) - mean * mean;
        float rstd = rsqrtf(var + 1e-5f);
        const float4* wv4 = reinterpret_cast<const float4*>(lnw) + sub * 4;
        const float4* bv4 = reinterpret_cast<const float4*>(lnb) + sub * 4;
        float4 xq[4] = {x0, x1, x2, x3};
        #pragma unroll
        for (int q = 0; q < 4; q++) {
            float4 wv = wv4[q], bv = bv4[q];
            uint4 tv;
            tv.x = f2tf32((xq[q].x - mean) * rstd * wv.x + bv.x);
            tv.y = f2tf32((xq[q].y - mean) * rstd * wv.y + bv.y);
            tv.z = f2tf32((xq[q].z - mean) * rstd * wv.z + bv.z);
            tv.w = f2tf32((xq[q].w - mean) * rstd * wv.w + bv.w);
            *reinterpret_cast<uint4*>(&Asu[row * PA_STR + sub * 16 + q * 4]) = tv;
        }
    }

    #pragma unroll 1
    for (int cg = 0; cg < 2; cg++) {
        float acc[5][4] = {};
        #pragma unroll
        for (int kh = 0; kh < 2; kh++) {
            if (cg | kh) __syncthreads();   // previous B panel fully consumed
            #pragma unroll
            for (int t = 0; t < 5; t++) {
                int idx = tid + t * 512;            // 2560 = 160 x 16 float4
                int rr = idx >> 4, c4 = idx & 15;
                int gc = cg * 160 + rr;
                const float* wrow;
                if (gc < 128)      wrow = Wq + (size_t)gc * CZ;
                else if (gc < 160) wrow = Wk + (size_t)(gc - 128) * CZ;
                else if (gc < 192) wrow = Wv + (size_t)(gc - 160) * CZ;
                else               wrow = Wg + (size_t)(gc - 192) * CZ;
                float4 v = reinterpret_cast<const float4*>(wrow)[kh * 16 + c4];
                *reinterpret_cast<uint4*>(&Bsu[rr * PB_STR + c4 * 4]) = f2tf32x4(v);
            }
            __syncthreads();
            #pragma unroll
            for (int ks = 0; ks < 8; ks++) {
                int k0 = ks * 8;
                int ka = kh * 64 + k0;
                uint32_t ah[4];
                ah[0] = Asu[(m0 + r) * PA_STR + ka + c];
                ah[1] = Asu[(m0 + r + 8) * PA_STR + ka + c];
                ah[2] = Asu[(m0 + r) * PA_STR + ka + c + 4];
                ah[3] = Asu[(m0 + r + 8) * PA_STR + ka + c + 4];
                #pragma unroll
                for (int nt = 0; nt < 5; nt++) {
                    uint32_t b[2];
                    b[0] = Bsu[(n0 + nt * 8 + r) * PB_STR + k0 + c];
                    b[1] = Bsu[(n0 + nt * 8 + r) * PB_STR + k0 + c + 4];
                    mma_tf32(acc[nt], ah, b);
                }
            }
        }
        #pragma unroll
        for (int nt = 0; nt < 5; nt++) {
            int gc = cg * 160 + n0 + nt * 8 + c * 2;
            #pragma unroll
            for (int half = 0; half < 2; half++) {
                size_t row = (size_t)rowBase + m0 + r + half * 8;
                float2 v = make_float2(acc[nt][half * 2], acc[nt][half * 2 + 1]);
                if (gc < 128) {
                    // pre-scale + pre-round q to tf32 (bit-identical to rounding in attn)
                    v.x = __uint_as_float(f2tf32(v.x * qscale));
                    v.y = __uint_as_float(f2tf32(v.y * qscale));
                    *reinterpret_cast<float2*>(&g_q[row * CZ + gc]) = v;
                } else if (gc < 160) {
                    v.x = __uint_as_float(f2tf32(v.x));
                    v.y = __uint_as_float(f2tf32(v.y));
                    *reinterpret_cast<float2*>(&g_k[row * CH + (gc - 128)]) = v;
                } else if (gc < 192) {
                    v.x = __uint_as_float(f2tf32(v.x));
                    v.y = __uint_as_float(f2tf32(v.y));
                    *reinterpret_cast<float2*>(&g_v[row * CH + (gc - 160)]) = v;
                } else {
                    int cc = gc - 192;
                    v.x = 1.0f / (1.0f + __expf(-(v.x + bg[cc])));
                    v.y = 1.0f / (1.0f + __expf(-(v.y + bg[cc + 1])));
                    *reinterpret_cast<float2*>(&g_g[row * CZ + cc]) = v;
                }
            }
        }
    }
}

// ---------------- kernel 2: attention + fused out-proj (R13 schedule; copy-only staging) ----------------
#define QSTR    132
#define KSTR    36
#define VSTR    40
#define PT_STR  36
#define OSTR    132
#define RED_OFF 0                        // 256 floats [wn][64]
#define Q_OFF   512                      // 64 x 132
#define K_OFF   (Q_OFF + 64*QSTR)        // 384 x 36  (later: Wo 128 x 132 tf32)
#define V_OFF   (K_OFF + 384*KSTR)       // 384 x 40
#define PT_OFF  (V_OFF + 384*VSTR)       // 4 x 64 x 36
#define O_OFF   (PT_OFF + 4*64*PT_STR)   // 64 x 132 fp32
#define ATTN_SMEM_F (O_OFF + 64*OSTR)    // 55808 floats
#define ATTN_SMEM_B (ATTN_SMEM_F * 4)    // 223232 B

__global__ void __launch_bounds__(512, 1) attn_mma_kernel(const float* __restrict__ Wo,
                                                          const float* __restrict__ bo,
                                                          float* __restrict__ out)
{
    extern __shared__ float smf[];
    uint32_t* smu = reinterpret_cast<uint32_t*>(smf);
    const int tid  = threadIdx.x;
    const int wid  = tid >> 5;
    const int lane = tid & 31;
    const int wm = wid & 3;
    const int wn = wid >> 2;
    const int r  = lane >> 2;
    const int c  = lane & 3;
    const int m0 = wm * 16;
    const int i  = blockIdx.x;
    const int jt = blockIdx.y;

    const size_t qrow0 = (size_t)i * S_DIM + jt * 64;
    const size_t kr0   = (size_t)i * S_DIM;

    // ---- stage Q (pre-rounded tf32): pure LDG.128 -> STS.128 copy ----
    #pragma unroll
    for (int t = 0; t < 4; t++) {
        int idx = tid + t * 512;
        int rr = idx >> 5, c4 = idx & 31;
        uint4 v = *reinterpret_cast<const uint4*>(&g_q[(qrow0 + rr) * CZ + c4 * 4]);
        *reinterpret_cast<uint4*>(&smu[Q_OFF + rr * QSTR + c4 * 4]) = v;
    }
    // ---- stage K, V (pre-rounded tf32): pure copies ----
    #pragma unroll
    for (int t = 0; t < 6; t++) {
        int idx = tid + t * 512;
        int rr = idx >> 3, c4 = idx & 7;
        uint4 k4 = *reinterpret_cast<const uint4*>(&g_k[(kr0 + rr) * CH + c4 * 4]);
        *reinterpret_cast<uint4*>(&smu[K_OFF + rr * KSTR + c4 * 4]) = k4;
        uint4 v4 = *reinterpret_cast<const uint4*>(&g_v[(kr0 + rr) * CH + c4 * 4]);
        *reinterpret_cast<uint4*>(&smu[V_OFF + rr * VSTR + c4 * 4]) = v4;
    }
    __syncthreads();

    const int srcA = (lane & ~3) | (c >> 1);
    const int srcB = srcA + 2;
    const bool odd = (c & 1) != 0;

    for (int h = 0; h < H_DIM; h++) {
        uint32_t afrag[4][4];
        #pragma unroll
        for (int kc = 0; kc < 4; kc++) {
            int base = Q_OFF + h * CH + kc * 8 + c;
            afrag[kc][0] = smu[base + (m0 + r) * QSTR];
            afrag[kc][1] = smu[base + (m0 + r + 8) * QSTR];
            afrag[kc][2] = smu[base + (m0 + r) * QSTR + 4];
            afrag[kc][3] = smu[base + (m0 + r + 8) * QSTR + 4];
        }
        float acc1[6][2][4] = {};
        #pragma unroll
        for (int kt = 0; kt < 6; kt++) {
            #pragma unroll
            for (int kc = 0; kc < 4; kc++) {
                #pragma unroll
                for (int j = 0; j < 2; j++) {
                    int n = kt * 64 + wn * 16 + j * 8;
                    uint32_t b[2];
                    b[0] = smu[K_OFF + (n + r) * KSTR + kc * 8 + c];
                    b[1] = smu[K_OFF + (n + r) * KSTR + kc * 8 + c + 4];
                    mma_tf32(acc1[kt][j], afrag[kc], b);
                }
            }
        }
        float rs0 = 0.0f, rs1 = 0.0f;
        #pragma unroll
        for (int kt = 0; kt < 6; kt++) {
            #pragma unroll
            for (int j = 0; j < 2; j++) {
                acc1[kt][j][0] = __expf(acc1[kt][j][0]);
                acc1[kt][j][1] = __expf(acc1[kt][j][1]);
                acc1[kt][j][2] = __expf(acc1[kt][j][2]);
                acc1[kt][j][3] = __expf(acc1[kt][j][3]);
                rs0 += acc1[kt][j][0] + acc1[kt][j][1];
                rs1 += acc1[kt][j][2] + acc1[kt][j][3];
            }
        }
        rs0 += __shfl_xor_sync(0xffffffffu, rs0, 1);
        rs0 += __shfl_xor_sync(0xffffffffu, rs0, 2);
        rs1 += __shfl_xor_sync(0xffffffffu, rs1, 1);
        rs1 += __shfl_xor_sync(0xffffffffu, rs1, 2);
        // ---- GEMM2 split-K with register P (C->A via quad shuffles) ----
        float acc2[4][4] = {};
        #pragma unroll
        for (int kt = 0; kt < 6; kt++) {
            #pragma unroll
            for (int j = 0; j < 2; j++) {
                float e0 = acc1[kt][j][0], e1 = acc1[kt][j][1];
                float e2 = acc1[kt][j][2], e3 = acc1[kt][j][3];
                float x0 = __shfl_sync(0xffffffffu, e0, srcA);
                float x1 = __shfl_sync(0xffffffffu, e1, srcA);
                float x2 = __shfl_sync(0xffffffffu, e2, srcA);
                float x3 = __shfl_sync(0xffffffffu, e3, srcA);
                float y0 = __shfl_sync(0xffffffffu, e0, srcB);
                float y1 = __shfl_sync(0xffffffffu, e1, srcB);
                float y2 = __shfl_sync(0xffffffffu, e2, srcB);
                float y3 = __shfl_sync(0xffffffffu, e3, srcB);
                uint32_t a[4];
                a[0] = f2tf32(odd ? x1 : x0);
                a[1] = f2tf32(odd ? x3 : x2);
                a[2] = f2tf32(odd ? y1 : y0);
                a[3] = f2tf32(odd ? y3 : y2);
                int k0 = kt * 64 + wn * 16 + j * 8;
                #pragma unroll
                for (int nt = 0; nt < 4; nt++) {
                    uint32_t b[2];
                    b[0] = smu[V_OFF + (k0 + c) * VSTR + nt * 8 + r];
                    b[1] = smu[V_OFF + (k0 + c + 4) * VSTR + nt * 8 + r];
                    mma_tf32(acc2[nt], a, b);
                }
            }
        }
        // ---- DELAYED barrier: previous head's reduce must finish before PT/red rewrite ----
        if (h) __syncthreads();
        if (c == 0) {
            smf[RED_OFF + wn * 64 + m0 + r] = rs0;
            smf[RED_OFF + wn * 64 + m0 + 8 + r] = rs1;
        }
        #pragma unroll
        for (int nt = 0; nt < 4; nt++) {
            int col = nt * 8 + c * 2;
            float* base = &smf[PT_OFF + wn * (64 * PT_STR)];
            *reinterpret_cast<float2*>(&base[(m0 + r) * PT_STR + col]) =
                make_float2(acc2[nt][0], acc2[nt][1]);
            *reinterpret_cast<float2*>(&base[(m0 + 8 + r) * PT_STR + col]) =
                make_float2(acc2[nt][2], acc2[nt][3]);
        }
        __syncthreads();
        // ---- reduce partials, inv row-sum, gate -> O smem ----
        {
            int row = tid >> 3;
            int c0  = (tid & 7) * 4;
            float4 s0 = *reinterpret_cast<const float4*>(&smf[PT_OFF + 0 * (64*PT_STR) + row * PT_STR + c0]);
            float4 s1 = *reinterpret_cast<const float4*>(&smf[PT_OFF + 1 * (64*PT_STR) + row * PT_STR + c0]);
            float4 s2 = *reinterpret_cast<const float4*>(&smf[PT_OFF + 2 * (64*PT_STR) + row * PT_STR + c0]);
            float4 s3 = *reinterpret_cast<const float4*>(&smf[PT_OFF + 3 * (64*PT_STR) + row * PT_STR + c0]);
            float total = smf[RED_OFF + row] + smf[RED_OFF + 64 + row]
                        + smf[RED_OFF + 128 + row] + smf[RED_OFF + 192 + row];
            float inv = 1.0f / total;
            float4 g = *reinterpret_cast<const float4*>(&g_g[(qrow0 + row) * CZ + h * CH + c0]);
            float4 o;
            o.x = (s0.x + s1.x + s2.x + s3.x) * inv * g.x;
            o.y = (s0.y + s1.y + s2.y + s3.y) * inv * g.y;
            o.z = (s0.z + s1.z + s2.z + s3.z) * inv * g.z;
            o.w = (s0.w + s1.w + s2.w + s3.w) * inv * g.w;
            *reinterpret_cast<float4*>(&smf[O_OFF + row * OSTR + h * CH + c0]) = o;
        }
        // no sync here — delayed barrier at top of next head protects PT/red
    }

    __syncthreads();   // all reduces done (O complete) + all PT/KV reads done
    // ---- stage Wo (tf32) over dead K/V region (stride 132), STS.128 ----
    #pragma unroll
    for (int t = 0; t < 8; t++) {
        int idx = tid + t * 512;
        int rr = idx >> 5, c4 = idx & 31;
        float4 v = reinterpret_cast<const float4*>(Wo + (size_t)rr * CZ)[c4];
        *reinterpret_cast<uint4*>(&smu[K_OFF + rr * QSTR + c4 * 4]) = f2tf32x4(v);
    }
    __syncthreads();

    // ---- fused output projection: out = O @ Wo^T + bo (hi/lo exact A) ----
    float acco[4][4] = {};
    const int n0o = wn * 32;
    #pragma unroll
    for (int ks = 0; ks < 16; ks++) {
        int k0 = ks * 8;
        uint32_t ah[4], al[4];
        load_split(smf,
            O_OFF + (m0 + r) * OSTR + k0 + c,     O_OFF + (m0 + r + 8) * OSTR + k0 + c,
            O_OFF + (m0 + r) * OSTR + k0 + c + 4, O_OFF + (m0 + r + 8) * OSTR + k0 + c + 4,
            ah, al);
        #pragma unroll
        for (int nt = 0; nt < 4; nt++) {
            uint32_t b[2];
            b[0] = smu[K_OFF + (n0o + nt * 8 + r) * QSTR + k0 + c];
            b[1] = smu[K_OFF + (n0o + nt * 8 + r) * QSTR + k0 + c + 4];
            mma_tf32(acco[nt], ah, b);
            mma_tf32(acco[nt], al, b);
        }
    }
    #pragma unroll
    for (int nt = 0; nt < 4; nt++) {
        int gc = n0o + nt * 8 + c * 2;
        float bx = bo[gc], by = bo[gc + 1];
        #pragma unroll
        for (int half = 0; half < 2; half++) {
            size_t row = qrow0 + m0 + r + half * 8;
            float2 v = make_float2(acco[nt][half * 2] + bx, acco[nt][half * 2 + 1] + by);
            *reinterpret_cast<float2*>(&out[row * CZ + gc]) = v;
        }
    }
}

// ---------------- launch ----------------
extern "C" void kernel_launch(void* const* d_in, const int* in_sizes, int n_in,
                              void* d_out, int out_size)
{
    const float* z   = (const float*)d_in[0];
    const float* lnw = (const float*)d_in[1];
    const float* lnb = (const float*)d_in[2];
    const float* Wq  = (const float*)d_in[3];
    const float* Wk  = (const float*)d_in[4];
    const float* Wv  = (const float*)d_in[5];
    // d_in[6] = Wb : bias broadcasts along the key axis -> softmax-invariant -> unused
    const float* Wg  = (const float*)d_in[7];
    const float* bg  = (const float*)d_in[8];
    const float* Wo  = (const float*)d_in[9];
    const float* bo  = (const float*)d_in[10];
    float* out = (float*)d_out;
    (void)in_sizes; (void)n_in; (void)out_size;

    cudaFuncSetAttribute(proj_mma, cudaFuncAttributeMaxDynamicSharedMemorySize, PROJ_SMEM);
    cudaFuncSetAttribute(attn_mma_kernel, cudaFuncAttributeMaxDynamicSharedMemorySize, ATTN_SMEM_B);

    proj_mma<<<NROWS / 64, 512, PROJ_SMEM>>>(z, lnw, lnb, Wq, Wk, Wv, Wg, bg);
    attn_mma_kernel<<<dim3(S_DIM, 6), 512, ATTN_SMEM_B>>>(Wo, bo, out);
}

// round 16
// speedup vs baseline: 1.0207x; 1.0207x over previous
#include <cuda_runtime.h>
#include <math.h>
#include <stdint.h>

#define S_DIM  384
#define CZ     128
#define H_DIM  4
#define CH     32
#define NROWS  (S_DIM*S_DIM)   // 147456

// ---------------- scratch (device globals; allocation-free) ----------------
__device__ float g_q [(size_t)NROWS*CZ];   // tf32(q * scale)  (col = h*32+c)
__device__ float g_g [(size_t)NROWS*CZ];   // sigmoid gate (fp32)
__device__ float g_k [(size_t)NROWS*CH];   // tf32(k)
__device__ float g_v [(size_t)NROWS*CH];   // tf32(v)
__device__ float g_wcat[320*CZ];           // tf32 weights: [Wq;Wk;Wv;Wg]
__device__ float g_wo  [CZ*CZ];            // tf32(Wo)

// ---------------- helpers ----------------
__device__ __forceinline__ uint32_t f2tf32(float f) {
    uint32_t u; asm("cvt.rna.tf32.f32 %0, %1;" : "=r"(u) : "f"(f)); return u;
}
__device__ __forceinline__ void mma_tf32(float* d, const uint32_t* a, const uint32_t* b) {
    asm volatile(
        "mma.sync.aligned.m16n8k8.row.col.f32.tf32.tf32.f32 "
        "{%0,%1,%2,%3}, {%4,%5,%6,%7}, {%8,%9}, {%0,%1,%2,%3};\n"
        : "+f"(d[0]), "+f"(d[1]), "+f"(d[2]), "+f"(d[3])
        : "r"(a[0]), "r"(a[1]), "r"(a[2]), "r"(a[3]), "r"(b[0]), "r"(b[1]));
}
__device__ __forceinline__ void load_split(const float* smf, int i0, int i1, int i2, int i3,
                                           uint32_t* ah, uint32_t* al) {
    float a0 = smf[i0], a1 = smf[i1], a2 = smf[i2], a3 = smf[i3];
    ah[0] = f2tf32(a0); al[0] = f2tf32(a0 - __uint_as_float(ah[0]));
    ah[1] = f2tf32(a1); al[1] = f2tf32(a1 - __uint_as_float(ah[1]));
    ah[2] = f2tf32(a2); al[2] = f2tf32(a2 - __uint_as_float(ah[2]));
    ah[3] = f2tf32(a3); al[3] = f2tf32(a3 - __uint_as_float(ah[3]));
}
__device__ __forceinline__ uint32_t smem_u32(const void* p) {
    uint32_t a;
    asm("{ .reg .u64 t; cvta.to.shared.u64 t, %1; cvt.u32.u64 %0, t; }" : "=r"(a) : "l"(p));
    return a;
}

// ---------------- kernel 0: pre-round weights to tf32 ----------------
__global__ void prep_w(const float* __restrict__ Wq, const float* __restrict__ Wk,
                       const float* __restrict__ Wv, const float* __restrict__ Wg,
                       const float* __restrict__ Wo)
{
    int row = blockIdx.x;        // 0..447
    int c   = threadIdx.x;       // 0..127
    const float* src; float* dst;
    if (row < 128)      { src = Wq + (size_t)row * CZ;        dst = g_wcat + (size_t)row * CZ; }
    else if (row < 160) { src = Wk + (size_t)(row-128) * CZ;  dst = g_wcat + (size_t)row * CZ; }
    else if (row < 192) { src = Wv + (size_t)(row-160) * CZ;  dst = g_wcat + (size_t)row * CZ; }
    else if (row < 320) { src = Wg + (size_t)(row-192) * CZ;  dst = g_wcat + (size_t)row * CZ; }
    else                { src = Wo + (size_t)(row-320) * CZ;  dst = g_wo + (size_t)(row-320) * CZ; }
    dst[c] = __uint_as_float(f2tf32(src[c]));
}

// ---------------- kernel 1: LayerNorm + fused projections (cp.async pipelined) ----------------
// CTA = 64 rows, all 320 cols (cg folded in quarter loop). B quarters (160x32,
// stride 36, pre-rounded tf32 weights) double-buffered via cp.async.
#define PA_STR 132
#define PBQ_STR 36
#define PBQ_BUF (160*PBQ_STR)
#define PROJ_SMEM (64*PA_STR*4 + 2*PBQ_BUF*4)   // 33792 + 46080 = 79872 B
__global__ void __launch_bounds__(512, 2) proj_mma(const float* __restrict__ z,
                                                   const float* __restrict__ lnw,
                                                   const float* __restrict__ lnb,
                                                   const float* __restrict__ bg)
{
    extern __shared__ float sm[];
    uint32_t* Asu = reinterpret_cast<uint32_t*>(sm);                 // 64 x 132 tf32 (zn)
    uint32_t* Bsu = reinterpret_cast<uint32_t*>(sm + 64 * PA_STR);   // 2 x 160 x 36 tf32
    const uint32_t bs_base = smem_u32(Bsu);

    const int tid  = threadIdx.x;
    const int wid  = tid >> 5;
    const int lane = tid & 31;
    const int r = lane >> 2, c = lane & 3;
    const int wm = wid & 3, wn = wid >> 2;
    const int m0 = wm * 16, n0 = wn * 40;
    const int rowBase = blockIdx.x * 64;
    const float qscale = 0.17677669529663689f;  // 1/sqrt(32)

    // ---- prefetch helper: quarter q -> buffer buf ----
    auto prefetch = [&](int q, int buf) {
        int cgq = q >> 2, kq = q & 3;
        #pragma unroll
        for (int t = 0; t < 3; t++) {
            int idx = tid + t * 512;             // need 1280 = 160 rows x 8 float4
            if (idx < 1280) {
                int rr = idx >> 3, c4 = idx & 7;
                const float* src = g_wcat + (size_t)(cgq * 160 + rr) * CZ + kq * 32 + c4 * 4;
                uint32_t dst = bs_base + (uint32_t)(buf * PBQ_BUF + rr * PBQ_STR + c4 * 4) * 4u;
                asm volatile("cp.async.ca.shared.global [%0], [%1], 16;" :: "r"(dst), "l"(src));
            }
        }
        asm volatile("cp.async.commit_group;");
    };

    prefetch(0, 0);

    // ---- fused LayerNorm -> tf32 zn in smem (overlaps cp.async of quarter 0) ----
    {
        int row = tid >> 3;
        int sub = tid & 7;
        const float4* zr = reinterpret_cast<const float4*>(z + (size_t)(rowBase + row) * CZ) + sub * 4;
        float4 x0 = zr[0], x1 = zr[1], x2 = zr[2], x3 = zr[3];
        float s  = x0.x+x0.y+x0.z+x0.w + x1.x+x1.y+x1.z+x1.w
                 + x2.x+x2.y+x2.z+x2.w + x3.x+x3.y+x3.z+x3.w;
        float ss = x0.x*x0.x+x0.y*x0.y+x0.z*x0.z+x0.w*x0.w
                 + x1.x*x1.x+x1.y*x1.y+x1.z*x1.z+x1.w*x1.w
                 + x2.x*x2.x+x2.y*x2.y+x2.z*x2.z+x2.w*x2.w
                 + x3.x*x3.x+x3.y*x3.y+x3.z*x3.z+x3.w*x3.w;
        #pragma unroll
        for (int o = 1; o < 8; o <<= 1) {
            s  += __shfl_xor_sync(0xffffffffu, s,  o);
            ss += __shfl_xor_sync(0xffffffffu, ss, o);
        }
        float mean = s * (1.0f / CZ);
        float var  = ss * (1.0f / CZ) - mean * mean;
        float rstd = rsqrtf(var + 1e-5f);
        const float4* wv4 = reinterpret_cast<const float4*>(lnw) + sub * 4;
        const float4* bv4 = reinterpret_cast<const float4*>(lnb) + sub * 4;
        float4 xq[4] = {x0, x1, x2, x3};
        #pragma unroll
        for (int q = 0; q < 4; q++) {
            float4 wv = wv4[q], bv = bv4[q];
            uint4 tv;
            tv.x = f2tf32((xq[q].x - mean) * rstd * wv.x + bv.x);
            tv.y = f2tf32((xq[q].y - mean) * rstd * wv.y + bv.y);
            tv.z = f2tf32((xq[q].z - mean) * rstd * wv.z + bv.z);
            tv.w = f2tf32((xq[q].w - mean) * rstd * wv.w + bv.w);
            *reinterpret_cast<uint4*>(&Asu[row * PA_STR + sub * 16 + q * 4]) = tv;
        }
    }

    float acc[5][4] = {};
    #pragma unroll 1
    for (int q = 0; q < 8; q++) {
        if (q < 7) prefetch(q + 1, (q + 1) & 1);
        else       asm volatile("cp.async.commit_group;");   // empty group keeps wait count uniform
        asm volatile("cp.async.wait_group 1;");
        __syncthreads();     // quarter q resident; also covers LN A-staging at q=0
        const int buf = q & 1;
        const int kqb = (q & 3) * 32;
        #pragma unroll
        for (int ks = 0; ks < 4; ks++) {
            int k0 = ks * 8;
            int ka = kqb + k0;
            uint32_t ah[4];
            ah[0] = Asu[(m0 + r) * PA_STR + ka + c];
            ah[1] = Asu[(m0 + r + 8) * PA_STR + ka + c];
            ah[2] = Asu[(m0 + r) * PA_STR + ka + c + 4];
            ah[3] = Asu[(m0 + r + 8) * PA_STR + ka + c + 4];
            #pragma unroll
            for (int nt = 0; nt < 5; nt++) {
                uint32_t b[2];
                b[0] = Bsu[buf * PBQ_BUF + (n0 + nt * 8 + r) * PBQ_STR + k0 + c];
                b[1] = Bsu[buf * PBQ_BUF + (n0 + nt * 8 + r) * PBQ_STR + k0 + c + 4];
                mma_tf32(acc[nt], ah, b);
            }
        }
        // ---- epilogue at end of each cg (q==3, q==7) ----
        if ((q & 3) == 3) {
            const int cg = q >> 2;
            #pragma unroll
            for (int nt = 0; nt < 5; nt++) {
                int gc = cg * 160 + n0 + nt * 8 + c * 2;
                #pragma unroll
                for (int half = 0; half < 2; half++) {
                    size_t row = (size_t)rowBase + m0 + r + half * 8;
                    float2 v = make_float2(acc[nt][half * 2], acc[nt][half * 2 + 1]);
                    if (gc < 128) {
                        v.x = __uint_as_float(f2tf32(v.x * qscale));
                        v.y = __uint_as_float(f2tf32(v.y * qscale));
                        *reinterpret_cast<float2*>(&g_q[row * CZ + gc]) = v;
                    } else if (gc < 160) {
                        v.x = __uint_as_float(f2tf32(v.x));
                        v.y = __uint_as_float(f2tf32(v.y));
                        *reinterpret_cast<float2*>(&g_k[row * CH + (gc - 128)]) = v;
                    } else if (gc < 192) {
                        v.x = __uint_as_float(f2tf32(v.x));
                        v.y = __uint_as_float(f2tf32(v.y));
                        *reinterpret_cast<float2*>(&g_v[row * CH + (gc - 160)]) = v;
                    } else {
                        int cc = gc - 192;
                        v.x = 1.0f / (1.0f + __expf(-(v.x + bg[cc])));
                        v.y = 1.0f / (1.0f + __expf(-(v.y + bg[cc + 1])));
                        *reinterpret_cast<float2*>(&g_g[row * CZ + cc]) = v;
                    }
                }
            }
            #pragma unroll
            for (int nt = 0; nt < 5; nt++) {
                acc[nt][0] = 0.0f; acc[nt][1] = 0.0f;
                acc[nt][2] = 0.0f; acc[nt][3] = 0.0f;
            }
        }
        __syncthreads();     // all reads of buf done before iter q+2 overwrites it
    }
}

// ---------------- kernel 2: attention + fused out-proj (R15-exact; Wo copy-only) ----------------
#define QSTR    132
#define KSTR    36
#define VSTR    40
#define PT_STR  36
#define OSTR    132
#define RED_OFF 0                        // 256 floats [wn][64]
#define Q_OFF   512                      // 64 x 132
#define K_OFF   (Q_OFF + 64*QSTR)        // 384 x 36  (later: Wo 128 x 132 tf32)
#define V_OFF   (K_OFF + 384*KSTR)       // 384 x 40
#define PT_OFF  (V_OFF + 384*VSTR)       // 4 x 64 x 36
#define O_OFF   (PT_OFF + 4*64*PT_STR)   // 64 x 132 fp32
#define ATTN_SMEM_F (O_OFF + 64*OSTR)    // 55808 floats
#define ATTN_SMEM_B (ATTN_SMEM_F * 4)    // 223232 B

__global__ void __launch_bounds__(512, 1) attn_mma_kernel(const float* __restrict__ bo,
                                                          float* __restrict__ out)
{
    extern __shared__ float smf[];
    uint32_t* smu = reinterpret_cast<uint32_t*>(smf);
    const int tid  = threadIdx.x;
    const int wid  = tid >> 5;
    const int lane = tid & 31;
    const int wm = wid & 3;
    const int wn = wid >> 2;
    const int r  = lane >> 2;
    const int c  = lane & 3;
    const int m0 = wm * 16;
    const int i  = blockIdx.x;
    const int jt = blockIdx.y;

    const size_t qrow0 = (size_t)i * S_DIM + jt * 64;
    const size_t kr0   = (size_t)i * S_DIM;

    // ---- stage Q (pre-rounded tf32): pure LDG.128 -> STS.128 copy ----
    #pragma unroll
    for (int t = 0; t < 4; t++) {
        int idx = tid + t * 512;
        int rr = idx >> 5, c4 = idx & 31;
        uint4 v = *reinterpret_cast<const uint4*>(&g_q[(qrow0 + rr) * CZ + c4 * 4]);
        *reinterpret_cast<uint4*>(&smu[Q_OFF + rr * QSTR + c4 * 4]) = v;
    }
    // ---- stage K, V (pre-rounded tf32): pure copies ----
    #pragma unroll
    for (int t = 0; t < 6; t++) {
        int idx = tid + t * 512;
        int rr = idx >> 3, c4 = idx & 7;
        uint4 k4 = *reinterpret_cast<const uint4*>(&g_k[(kr0 + rr) * CH + c4 * 4]);
        *reinterpret_cast<uint4*>(&smu[K_OFF + rr * KSTR + c4 * 4]) = k4;
        uint4 v4 = *reinterpret_cast<const uint4*>(&g_v[(kr0 + rr) * CH + c4 * 4]);
        *reinterpret_cast<uint4*>(&smu[V_OFF + rr * VSTR + c4 * 4]) = v4;
    }
    __syncthreads();

    const int srcA = (lane & ~3) | (c >> 1);
    const int srcB = srcA + 2;
    const bool odd = (c & 1) != 0;

    for (int h = 0; h < H_DIM; h++) {
        uint32_t afrag[4][4];
        #pragma unroll
        for (int kc = 0; kc < 4; kc++) {
            int base = Q_OFF + h * CH + kc * 8 + c;
            afrag[kc][0] = smu[base + (m0 + r) * QSTR];
            afrag[kc][1] = smu[base + (m0 + r + 8) * QSTR];
            afrag[kc][2] = smu[base + (m0 + r) * QSTR + 4];
            afrag[kc][3] = smu[base + (m0 + r + 8) * QSTR + 4];
        }
        float acc1[6][2][4] = {};
        #pragma unroll
        for (int kt = 0; kt < 6; kt++) {
            #pragma unroll
            for (int kc = 0; kc < 4; kc++) {
                #pragma unroll
                for (int j = 0; j < 2; j++) {
                    int n = kt * 64 + wn * 16 + j * 8;
                    uint32_t b[2];
                    b[0] = smu[K_OFF + (n + r) * KSTR + kc * 8 + c];
                    b[1] = smu[K_OFF + (n + r) * KSTR + kc * 8 + c + 4];
                    mma_tf32(acc1[kt][j], afrag[kc], b);
                }
            }
        }
        float rs0 = 0.0f, rs1 = 0.0f;
        #pragma unroll
        for (int kt = 0; kt < 6; kt++) {
            #pragma unroll
            for (int j = 0; j < 2; j++) {
                acc1[kt][j][0] = __expf(acc1[kt][j][0]);
                acc1[kt][j][1] = __expf(acc1[kt][j][1]);
                acc1[kt][j][2] = __expf(acc1[kt][j][2]);
                acc1[kt][j][3] = __expf(acc1[kt][j][3]);
                rs0 += acc1[kt][j][0] + acc1[kt][j][1];
                rs1 += acc1[kt][j][2] + acc1[kt][j][3];
            }
        }
        rs0 += __shfl_xor_sync(0xffffffffu, rs0, 1);
        rs0 += __shfl_xor_sync(0xffffffffu, rs0, 2);
        rs1 += __shfl_xor_sync(0xffffffffu, rs1, 1);
        rs1 += __shfl_xor_sync(0xffffffffu, rs1, 2);
        // ---- GEMM2 split-K with register P (C->A via quad shuffles) ----
        float acc2[4][4] = {};
        #pragma unroll
        for (int kt = 0; kt < 6; kt++) {
            #pragma unroll
            for (int j = 0; j < 2; j++) {
                float e0 = acc1[kt][j][0], e1 = acc1[kt][j][1];
                float e2 = acc1[kt][j][2], e3 = acc1[kt][j][3];
                float x0 = __shfl_sync(0xffffffffu, e0, srcA);
                float x1 = __shfl_sync(0xffffffffu, e1, srcA);
                float x2 = __shfl_sync(0xffffffffu, e2, srcA);
                float x3 = __shfl_sync(0xffffffffu, e3, srcA);
                float y0 = __shfl_sync(0xffffffffu, e0, srcB);
                float y1 = __shfl_sync(0xffffffffu, e1, srcB);
                float y2 = __shfl_sync(0xffffffffu, e2, srcB);
                float y3 = __shfl_sync(0xffffffffu, e3, srcB);
                uint32_t a[4];
                a[0] = f2tf32(odd ? x1 : x0);
                a[1] = f2tf32(odd ? x3 : x2);
                a[2] = f2tf32(odd ? y1 : y0);
                a[3] = f2tf32(odd ? y3 : y2);
                int k0 = kt * 64 + wn * 16 + j * 8;
                #pragma unroll
                for (int nt = 0; nt < 4; nt++) {
                    uint32_t b[2];
                    b[0] = smu[V_OFF + (k0 + c) * VSTR + nt * 8 + r];
                    b[1] = smu[V_OFF + (k0 + c + 4) * VSTR + nt * 8 + r];
                    mma_tf32(acc2[nt], a, b);
                }
            }
        }
        // ---- DELAYED barrier: previous head's reduce must finish before PT/red rewrite ----
        if (h) __syncthreads();
        if (c == 0) {
            smf[RED_OFF + wn * 64 + m0 + r] = rs0;
            smf[RED_OFF + wn * 64 + m0 + 8 + r] = rs1;
        }
        #pragma unroll
        for (int nt = 0; nt < 4; nt++) {
            int col = nt * 8 + c * 2;
            float* base = &smf[PT_OFF + wn * (64 * PT_STR)];
            *reinterpret_cast<float2*>(&base[(m0 + r) * PT_STR + col]) =
                make_float2(acc2[nt][0], acc2[nt][1]);
            *reinterpret_cast<float2*>(&base[(m0 + 8 + r) * PT_STR + col]) =
                make_float2(acc2[nt][2], acc2[nt][3]);
        }
        __syncthreads();
        // ---- reduce partials, inv row-sum, gate -> O smem ----
        {
            int row = tid >> 3;
            int c0  = (tid & 7) * 4;
            float4 s0 = *reinterpret_cast<const float4*>(&smf[PT_OFF + 0 * (64*PT_STR) + row * PT_STR + c0]);
            float4 s1 = *reinterpret_cast<const float4*>(&smf[PT_OFF + 1 * (64*PT_STR) + row * PT_STR + c0]);
            float4 s2 = *reinterpret_cast<const float4*>(&smf[PT_OFF + 2 * (64*PT_STR) + row * PT_STR + c0]);
            float4 s3 = *reinterpret_cast<const float4*>(&smf[PT_OFF + 3 * (64*PT_STR) + row * PT_STR + c0]);
            float total = smf[RED_OFF + row] + smf[RED_OFF + 64 + row]
                        + smf[RED_OFF + 128 + row] + smf[RED_OFF + 192 + row];
            float inv = 1.0f / total;
            float4 g = *reinterpret_cast<const float4*>(&g_g[(qrow0 + row) * CZ + h * CH + c0]);
            float4 o;
            o.x = (s0.x + s1.x + s2.x + s3.x) * inv * g.x;
            o.y = (s0.y + s1.y + s2.y + s3.y) * inv * g.y;
            o.z = (s0.z + s1.z + s2.z + s3.z) * inv * g.z;
            o.w = (s0.w + s1.w + s2.w + s3.w) * inv * g.w;
            *reinterpret_cast<float4*>(&smf[O_OFF + row * OSTR + h * CH + c0]) = o;
        }
        // no sync here — delayed barrier at top of next head protects PT/red
    }

    __syncthreads();   // all reduces done (O complete) + all PT/KV reads done
    // ---- stage Wo (pre-rounded tf32): pure copy over dead K/V region ----
    #pragma unroll
    for (int t = 0; t < 8; t++) {
        int idx = tid + t * 512;
        int rr = idx >> 5, c4 = idx & 31;
        uint4 v = *reinterpret_cast<const uint4*>(&g_wo[(size_t)rr * CZ + c4 * 4]);
        *reinterpret_cast<uint4*>(&smu[K_OFF + rr * QSTR + c4 * 4]) = v;
    }
    __syncthreads();

    // ---- fused output projection: out = O @ Wo^T + bo (hi/lo exact A) ----
    float acco[4][4] = {};
    const int n0o = wn * 32;
    #pragma unroll
    for (int ks = 0; ks < 16; ks++) {
        int k0 = ks * 8;
        uint32_t ah[4], al[4];
        load_split(smf,
            O_OFF + (m0 + r) * OSTR + k0 + c,     O_OFF + (m0 + r + 8) * OSTR + k0 + c,
            O_OFF + (m0 + r) * OSTR + k0 + c + 4, O_OFF + (m0 + r + 8) * OSTR + k0 + c + 4,
            ah, al);
        #pragma unroll
        for (int nt = 0; nt < 4; nt++) {
            uint32_t b[2];
            b[0] = smu[K_OFF + (n0o + nt * 8 + r) * QSTR + k0 + c];
            b[1] = smu[K_OFF + (n0o + nt * 8 + r) * QSTR + k0 + c + 4];
            mma_tf32(acco[nt], ah, b);
            mma_tf32(acco[nt], al, b);
        }
    }
    #pragma unroll
    for (int nt = 0; nt < 4; nt++) {
        int gc = n0o + nt * 8 + c * 2;
        float bx = bo[gc], by = bo[gc + 1];
        #pragma unroll
        for (int half = 0; half < 2; half++) {
            size_t row = qrow0 + m0 + r + half * 8;
            float2 v = make_float2(acco[nt][half * 2] + bx, acco[nt][half * 2 + 1] + by);
            *reinterpret_cast<float2*>(&out[row * CZ + gc]) = v;
        }
    }
}

// ---------------- launch ----------------
extern "C" void kernel_launch(void* const* d_in, const int* in_sizes, int n_in,
                              void* d_out, int out_size)
{
    const float* z   = (const float*)d_in[0];
    const float* lnw = (const float*)d_in[1];
    const float* lnb = (const float*)d_in[2];
    const float* Wq  = (const float*)d_in[3];
    const float* Wk  = (const float*)d_in[4];
    const float* Wv  = (const float*)d_in[5];
    // d_in[6] = Wb : bias broadcasts along the key axis -> softmax-invariant -> unused
    const float* Wg  = (const float*)d_in[7];
    const float* bg  = (const float*)d_in[8];
    const float* Wo  = (const float*)d_in[9];
    const float* bo  = (const float*)d_in[10];
    float* out = (float*)d_out;
    (void)in_sizes; (void)n_in; (void)out_size;

    cudaFuncSetAttribute(proj_mma, cudaFuncAttributeMaxDynamicSharedMemorySize, PROJ_SMEM);
    cudaFuncSetAttribute(attn_mma_kernel, cudaFuncAttributeMaxDynamicSharedMemorySize, ATTN_SMEM_B);

    prep_w<<<448, 128>>>(Wq, Wk, Wv, Wg, Wo);
    proj_mma<<<NROWS / 64, 512, PROJ_SMEM>>>(z, lnw, lnb, bg);
    attn_mma_kernel<<<dim3(S_DIM, 6), 512, ATTN_SMEM_B>>>(bo, out);
}

// round 17
// speedup vs baseline: 1.0226x; 1.0019x over previous
#include <cuda_runtime.h>
#include <math.h>
#include <stdint.h>

#define S_DIM  384
#define CZ     128
#define H_DIM  4
#define CH     32
#define NROWS  (S_DIM*S_DIM)   // 147456

// ---------------- scratch (device globals; allocation-free) ----------------
__device__ float g_q [(size_t)NROWS*CZ];   // tf32(q * scale * log2e)  (col = h*32+c)
__device__ float g_g [(size_t)NROWS*CZ];   // sigmoid gate (fp32)
__device__ float g_k [(size_t)NROWS*CH];   // tf32(k)
__device__ float g_v [(size_t)NROWS*CH];   // tf32(v)
__device__ float g_wcat[320*CZ];           // tf32 weights: [Wq;Wk;Wv;Wg]
__device__ float g_wo  [CZ*CZ];            // tf32(Wo)

// ---------------- helpers ----------------
__device__ __forceinline__ uint32_t f2tf32(float f) {
    uint32_t u; asm("cvt.rna.tf32.f32 %0, %1;" : "=r"(u) : "f"(f)); return u;
}
__device__ __forceinline__ void mma_tf32(float* d, const uint32_t* a, const uint32_t* b) {
    asm volatile(
        "mma.sync.aligned.m16n8k8.row.col.f32.tf32.tf32.f32 "
        "{%0,%1,%2,%3}, {%4,%5,%6,%7}, {%8,%9}, {%0,%1,%2,%3};\n"
        : "+f"(d[0]), "+f"(d[1]), "+f"(d[2]), "+f"(d[3])
        : "r"(a[0]), "r"(a[1]), "r"(a[2]), "r"(a[3]), "r"(b[0]), "r"(b[1]));
}
__device__ __forceinline__ void load_split(const float* smf, int i0, int i1, int i2, int i3,
                                           uint32_t* ah, uint32_t* al) {
    float a0 = smf[i0], a1 = smf[i1], a2 = smf[i2], a3 = smf[i3];
    ah[0] = f2tf32(a0); al[0] = f2tf32(a0 - __uint_as_float(ah[0]));
    ah[1] = f2tf32(a1); al[1] = f2tf32(a1 - __uint_as_float(ah[1]));
    ah[2] = f2tf32(a2); al[2] = f2tf32(a2 - __uint_as_float(ah[2]));
    ah[3] = f2tf32(a3); al[3] = f2tf32(a3 - __uint_as_float(ah[3]));
}
__device__ __forceinline__ uint32_t smem_u32(const void* p) {
    uint32_t a;
    asm("{ .reg .u64 t; cvta.to.shared.u64 t, %1; cvt.u32.u64 %0, t; }" : "=r"(a) : "l"(p));
    return a;
}

// ---------------- kernel 0: pre-round weights to tf32 ----------------
__global__ void prep_w(const float* __restrict__ Wq, const float* __restrict__ Wk,
                       const float* __restrict__ Wv, const float* __restrict__ Wg,
                       const float* __restrict__ Wo)
{
    int row = blockIdx.x;        // 0..447
    int c   = threadIdx.x;       // 0..127
    const float* src; float* dst;
    if (row < 128)      { src = Wq + (size_t)row * CZ;        dst = g_wcat + (size_t)row * CZ; }
    else if (row < 160) { src = Wk + (size_t)(row-128) * CZ;  dst = g_wcat + (size_t)row * CZ; }
    else if (row < 192) { src = Wv + (size_t)(row-160) * CZ;  dst = g_wcat + (size_t)row * CZ; }
    else if (row < 320) { src = Wg + (size_t)(row-192) * CZ;  dst = g_wcat + (size_t)row * CZ; }
    else                { src = Wo + (size_t)(row-320) * CZ;  dst = g_wo + (size_t)(row-320) * CZ; }
    dst[c] = __uint_as_float(f2tf32(src[c]));
}

// ---------------- kernel 1: LayerNorm + fused projections (cp.async pipelined) ----------------
#define PA_STR 132
#define PBQ_STR 36
#define PBQ_BUF (160*PBQ_STR)
#define PROJ_SMEM (64*PA_STR*4 + 2*PBQ_BUF*4)   // 79872 B
__global__ void __launch_bounds__(512, 2) proj_mma(const float* __restrict__ z,
                                                   const float* __restrict__ lnw,
                                                   const float* __restrict__ lnb,
                                                   const float* __restrict__ bg)
{
    extern __shared__ float sm[];
    uint32_t* Asu = reinterpret_cast<uint32_t*>(sm);                 // 64 x 132 tf32 (zn)
    uint32_t* Bsu = reinterpret_cast<uint32_t*>(sm + 64 * PA_STR);   // 2 x 160 x 36 tf32
    const uint32_t bs_base = smem_u32(Bsu);

    const int tid  = threadIdx.x;
    const int wid  = tid >> 5;
    const int lane = tid & 31;
    const int r = lane >> 2, c = lane & 3;
    const int wm = wid & 3, wn = wid >> 2;
    const int m0 = wm * 16, n0 = wn * 40;
    const int rowBase = blockIdx.x * 64;
    // 1/sqrt(32) * log2(e): folds the exp->exp2 conversion into q's pre-scale
    const float qscale = 0.25503488762748047f;

    auto prefetch = [&](int q, int buf) {
        int cgq = q >> 2, kq = q & 3;
        #pragma unroll
        for (int t = 0; t < 3; t++) {
            int idx = tid + t * 512;
            if (idx < 1280) {
                int rr = idx >> 3, c4 = idx & 7;
                const float* src = g_wcat + (size_t)(cgq * 160 + rr) * CZ + kq * 32 + c4 * 4;
                uint32_t dst = bs_base + (uint32_t)(buf * PBQ_BUF + rr * PBQ_STR + c4 * 4) * 4u;
                asm volatile("cp.async.ca.shared.global [%0], [%1], 16;" :: "r"(dst), "l"(src));
            }
        }
        asm volatile("cp.async.commit_group;");
    };

    prefetch(0, 0);

    // ---- fused LayerNorm -> tf32 zn in smem (overlaps cp.async of quarter 0) ----
    {
        int row = tid >> 3;
        int sub = tid & 7;
        const float4* zr = reinterpret_cast<const float4*>(z + (size_t)(rowBase + row) * CZ) + sub * 4;
        float4 x0 = zr[0], x1 = zr[1], x2 = zr[2], x3 = zr[3];
        float s  = x0.x+x0.y+x0.z+x0.w + x1.x+x1.y+x1.z+x1.w
                 + x2.x+x2.y+x2.z+x2.w + x3.x+x3.y+x3.z+x3.w;
        float ss = x0.x*x0.x+x0.y*x0.y+x0.z*x0.z+x0.w*x0.w
                 + x1.x*x1.x+x1.y*x1.y+x1.z*x1.z+x1.w*x1.w
                 + x2.x*x2.x+x2.y*x2.y+x2.z*x2.z+x2.w*x2.w
                 + x3.x*x3.x+x3.y*x3.y+x3.z*x3.z+x3.w*x3.w;
        #pragma unroll
        for (int o = 1; o < 8; o <<= 1) {
            s  += __shfl_xor_sync(0xffffffffu, s,  o);
            ss += __shfl_xor_sync(0xffffffffu, ss, o);
        }
        float mean = s * (1.0f / CZ);
        float var  = ss * (1.0f / CZ) - mean * mean;
        float rstd = rsqrtf(var + 1e-5f);
        const float4* wv4 = reinterpret_cast<const float4*>(lnw) + sub * 4;
        const float4* bv4 = reinterpret_cast<const float4*>(lnb) + sub * 4;
        float4 xq[4] = {x0, x1, x2, x3};
        #pragma unroll
        for (int q = 0; q < 4; q++) {
            float4 wv = wv4[q], bv = bv4[q];
            uint4 tv;
            tv.x = f2tf32((xq[q].x - mean) * rstd * wv.x + bv.x);
            tv.y = f2tf32((xq[q].y - mean) * rstd * wv.y + bv.y);
            tv.z = f2tf32((xq[q].z - mean) * rstd * wv.z + bv.z);
            tv.w = f2tf32((xq[q].w - mean) * rstd * wv.w + bv.w);
            *reinterpret_cast<uint4*>(&Asu[row * PA_STR + sub * 16 + q * 4]) = tv;
        }
    }

    float acc[5][4] = {};
    #pragma unroll 1
    for (int q = 0; q < 8; q++) {
        if (q < 7) prefetch(q + 1, (q + 1) & 1);
        else       asm volatile("cp.async.commit_group;");
        asm volatile("cp.async.wait_group 1;");
        __syncthreads();
        const int buf = q & 1;
        const int kqb = (q & 3) * 32;
        #pragma unroll
        for (int ks = 0; ks < 4; ks++) {
            int k0 = ks * 8;
            int ka = kqb + k0;
            uint32_t ah[4];
            ah[0] = Asu[(m0 + r) * PA_STR + ka + c];
            ah[1] = Asu[(m0 + r + 8) * PA_STR + ka + c];
            ah[2] = Asu[(m0 + r) * PA_STR + ka + c + 4];
            ah[3] = Asu[(m0 + r + 8) * PA_STR + ka + c + 4];
            #pragma unroll
            for (int nt = 0; nt < 5; nt++) {
                uint32_t b[2];
                b[0] = Bsu[buf * PBQ_BUF + (n0 + nt * 8 + r) * PBQ_STR + k0 + c];
                b[1] = Bsu[buf * PBQ_BUF + (n0 + nt * 8 + r) * PBQ_STR + k0 + c + 4];
                mma_tf32(acc[nt], ah, b);
            }
        }
        if ((q & 3) == 3) {
            const int cg = q >> 2;
            #pragma unroll
            for (int nt = 0; nt < 5; nt++) {
                int gc = cg * 160 + n0 + nt * 8 + c * 2;
                #pragma unroll
                for (int half = 0; half < 2; half++) {
                    size_t row = (size_t)rowBase + m0 + r + half * 8;
                    float2 v = make_float2(acc[nt][half * 2], acc[nt][half * 2 + 1]);
                    if (gc < 128) {
                        v.x = __uint_as_float(f2tf32(v.x * qscale));
                        v.y = __uint_as_float(f2tf32(v.y * qscale));
                        *reinterpret_cast<float2*>(&g_q[row * CZ + gc]) = v;
                    } else if (gc < 160) {
                        v.x = __uint_as_float(f2tf32(v.x));
                        v.y = __uint_as_float(f2tf32(v.y));
                        *reinterpret_cast<float2*>(&g_k[row * CH + (gc - 128)]) = v;
                    } else if (gc < 192) {
                        v.x = __uint_as_float(f2tf32(v.x));
                        v.y = __uint_as_float(f2tf32(v.y));
                        *reinterpret_cast<float2*>(&g_v[row * CH + (gc - 160)]) = v;
                    } else {
                        int cc = gc - 192;
                        v.x = 1.0f / (1.0f + __expf(-(v.x + bg[cc])));
                        v.y = 1.0f / (1.0f + __expf(-(v.y + bg[cc + 1])));
                        *reinterpret_cast<float2*>(&g_g[row * CZ + cc]) = v;
                    }
                }
            }
            #pragma unroll
            for (int nt = 0; nt < 5; nt++) {
                acc[nt][0] = 0.0f; acc[nt][1] = 0.0f;
                acc[nt][2] = 0.0f; acc[nt][3] = 0.0f;
            }
        }
        __syncthreads();
    }
}

// ---------------- kernel 2: attention + fused out-proj (exp2; jt-major grid for K/V L2 reuse) ----------------
#define QSTR    132
#define KSTR    36
#define VSTR    40
#define PT_STR  36
#define OSTR    132
#define RED_OFF 0                        // 256 floats [wn][64]
#define Q_OFF   512                      // 64 x 132
#define K_OFF   (Q_OFF + 64*QSTR)        // 384 x 36  (later: Wo 128 x 132 tf32)
#define V_OFF   (K_OFF + 384*KSTR)       // 384 x 40
#define PT_OFF  (V_OFF + 384*VSTR)       // 4 x 64 x 36
#define O_OFF   (PT_OFF + 4*64*PT_STR)   // 64 x 132 fp32
#define ATTN_SMEM_F (O_OFF + 64*OSTR)    // 55808 floats
#define ATTN_SMEM_B (ATTN_SMEM_F * 4)    // 223232 B

__global__ void __launch_bounds__(512, 1) attn_mma_kernel(const float* __restrict__ bo,
                                                          float* __restrict__ out)
{
    extern __shared__ float smf[];
    uint32_t* smu = reinterpret_cast<uint32_t*>(smf);
    const int tid  = threadIdx.x;
    const int wid  = tid >> 5;
    const int lane = tid & 31;
    const int wm = wid & 3;
    const int wn = wid >> 2;
    const int r  = lane >> 2;
    const int c  = lane & 3;
    const int m0 = wm * 16;
    const int jt = blockIdx.x;    // jt-major: the 6 CTAs sharing row i's K/V are
    const int i  = blockIdx.y;    // adjacent in the wave -> K/V served from L2

    const size_t qrow0 = (size_t)i * S_DIM + jt * 64;
    const size_t kr0   = (size_t)i * S_DIM;

    // ---- stage Q (pre-rounded tf32, includes scale*log2e): pure copy ----
    #pragma unroll
    for (int t = 0; t < 4; t++) {
        int idx = tid + t * 512;
        int rr = idx >> 5, c4 = idx & 31;
        uint4 v = *reinterpret_cast<const uint4*>(&g_q[(qrow0 + rr) * CZ + c4 * 4]);
        *reinterpret_cast<uint4*>(&smu[Q_OFF + rr * QSTR + c4 * 4]) = v;
    }
    // ---- stage K, V (pre-rounded tf32): pure copies ----
    #pragma unroll
    for (int t = 0; t < 6; t++) {
        int idx = tid + t * 512;
        int rr = idx >> 3, c4 = idx & 7;
        uint4 k4 = *reinterpret_cast<const uint4*>(&g_k[(kr0 + rr) * CH + c4 * 4]);
        *reinterpret_cast<uint4*>(&smu[K_OFF + rr * KSTR + c4 * 4]) = k4;
        uint4 v4 = *reinterpret_cast<const uint4*>(&g_v[(kr0 + rr) * CH + c4 * 4]);
        *reinterpret_cast<uint4*>(&smu[V_OFF + rr * VSTR + c4 * 4]) = v4;
    }
    __syncthreads();

    const int srcA = (lane & ~3) | (c >> 1);
    const int srcB = srcA + 2;
    const bool odd = (c & 1) != 0;

    for (int h = 0; h < H_DIM; h++) {
        uint32_t afrag[4][4];
        #pragma unroll
        for (int kc = 0; kc < 4; kc++) {
            int base = Q_OFF + h * CH + kc * 8 + c;
            afrag[kc][0] = smu[base + (m0 + r) * QSTR];
            afrag[kc][1] = smu[base + (m0 + r + 8) * QSTR];
            afrag[kc][2] = smu[base + (m0 + r) * QSTR + 4];
            afrag[kc][3] = smu[base + (m0 + r + 8) * QSTR + 4];
        }
        float acc1[6][2][4] = {};
        #pragma unroll
        for (int kt = 0; kt < 6; kt++) {
            #pragma unroll
            for (int kc = 0; kc < 4; kc++) {
                #pragma unroll
                for (int j = 0; j < 2; j++) {
                    int n = kt * 64 + wn * 16 + j * 8;
                    uint32_t b[2];
                    b[0] = smu[K_OFF + (n + r) * KSTR + kc * 8 + c];
                    b[1] = smu[K_OFF + (n + r) * KSTR + kc * 8 + c + 4];
                    mma_tf32(acc1[kt][j], afrag[kc], b);
                }
            }
        }
        float rs0 = 0.0f, rs1 = 0.0f;
        #pragma unroll
        for (int kt = 0; kt < 6; kt++) {
            #pragma unroll
            for (int j = 0; j < 2; j++) {
                acc1[kt][j][0] = exp2f(acc1[kt][j][0]);
                acc1[kt][j][1] = exp2f(acc1[kt][j][1]);
                acc1[kt][j][2] = exp2f(acc1[kt][j][2]);
                acc1[kt][j][3] = exp2f(acc1[kt][j][3]);
                rs0 += acc1[kt][j][0] + acc1[kt][j][1];
                rs1 += acc1[kt][j][2] + acc1[kt][j][3];
            }
        }
        rs0 += __shfl_xor_sync(0xffffffffu, rs0, 1);
        rs0 += __shfl_xor_sync(0xffffffffu, rs0, 2);
        rs1 += __shfl_xor_sync(0xffffffffu, rs1, 1);
        rs1 += __shfl_xor_sync(0xffffffffu, rs1, 2);
        // ---- GEMM2 split-K with register P (C->A via quad shuffles) ----
        float acc2[4][4] = {};
        #pragma unroll
        for (int kt = 0; kt < 6; kt++) {
            #pragma unroll
            for (int j = 0; j < 2; j++) {
                float e0 = acc1[kt][j][0], e1 = acc1[kt][j][1];
                float e2 = acc1[kt][j][2], e3 = acc1[kt][j][3];
                float x0 = __shfl_sync(0xffffffffu, e0, srcA);
                float x1 = __shfl_sync(0xffffffffu, e1, srcA);
                float x2 = __shfl_sync(0xffffffffu, e2, srcA);
                float x3 = __shfl_sync(0xffffffffu, e3, srcA);
                float y0 = __shfl_sync(0xffffffffu, e0, srcB);
                float y1 = __shfl_sync(0xffffffffu, e1, srcB);
                float y2 = __shfl_sync(0xffffffffu, e2, srcB);
                float y3 = __shfl_sync(0xffffffffu, e3, srcB);
                uint32_t a[4];
                a[0] = f2tf32(odd ? x1 : x0);
                a[1] = f2tf32(odd ? x3 : x2);
                a[2] = f2tf32(odd ? y1 : y0);
                a[3] = f2tf32(odd ? y3 : y2);
                int k0 = kt * 64 + wn * 16 + j * 8;
                #pragma unroll
                for (int nt = 0; nt < 4; nt++) {
                    uint32_t b[2];
                    b[0] = smu[V_OFF + (k0 + c) * VSTR + nt * 8 + r];
                    b[1] = smu[V_OFF + (k0 + c + 4) * VSTR + nt * 8 + r];
                    mma_tf32(acc2[nt], a, b);
                }
            }
        }
        // ---- DELAYED barrier: previous head's reduce must finish before PT/red rewrite ----
        if (h) __syncthreads();
        if (c == 0) {
            smf[RED_OFF + wn * 64 + m0 + r] = rs0;
            smf[RED_OFF + wn * 64 + m0 + 8 + r] = rs1;
        }
        #pragma unroll
        for (int nt = 0; nt < 4; nt++) {
            int col = nt * 8 + c * 2;
            float* base = &smf[PT_OFF + wn * (64 * PT_STR)];
            *reinterpret_cast<float2*>(&base[(m0 + r) * PT_STR + col]) =
                make_float2(acc2[nt][0], acc2[nt][1]);
            *reinterpret_cast<float2*>(&base[(m0 + 8 + r) * PT_STR + col]) =
                make_float2(acc2[nt][2], acc2[nt][3]);
        }
        __syncthreads();
        // ---- reduce partials, inv row-sum, gate -> O smem ----
        {
            int row = tid >> 3;
            int c0  = (tid & 7) * 4;
            float4 s0 = *reinterpret_cast<const float4*>(&smf[PT_OFF + 0 * (64*PT_STR) + row * PT_STR + c0]);
            float4 s1 = *reinterpret_cast<const float4*>(&smf[PT_OFF + 1 * (64*PT_STR) + row * PT_STR + c0]);
            float4 s2 = *reinterpret_cast<const float4*>(&smf[PT_OFF + 2 * (64*PT_STR) + row * PT_STR + c0]);
            float4 s3 = *reinterpret_cast<const float4*>(&smf[PT_OFF + 3 * (64*PT_STR) + row * PT_STR + c0]);
            float total = smf[RED_OFF + row] + smf[RED_OFF + 64 + row]
                        + smf[RED_OFF + 128 + row] + smf[RED_OFF + 192 + row];
            float inv = 1.0f / total;
            float4 g = *reinterpret_cast<const float4*>(&g_g[(qrow0 + row) * CZ + h * CH + c0]);
            float4 o;
            o.x = (s0.x + s1.x + s2.x + s3.x) * inv * g.x;
            o.y = (s0.y + s1.y + s2.y + s3.y) * inv * g.y;
            o.z = (s0.z + s1.z + s2.z + s3.z) * inv * g.z;
            o.w = (s0.w + s1.w + s2.w + s3.w) * inv * g.w;
            *reinterpret_cast<float4*>(&smf[O_OFF + row * OSTR + h * CH + c0]) = o;
        }
        // no sync here — delayed barrier at top of next head protects PT/red
    }

    __syncthreads();   // all reduces done (O complete) + all PT/KV reads done
    // ---- stage Wo (pre-rounded tf32): pure copy over dead K/V region ----
    #pragma unroll
    for (int t = 0; t < 8; t++) {
        int idx = tid + t * 512;
        int rr = idx >> 5, c4 = idx & 31;
        uint4 v = *reinterpret_cast<const uint4*>(&g_wo[(size_t)rr * CZ + c4 * 4]);
        *reinterpret_cast<uint4*>(&smu[K_OFF + rr * QSTR + c4 * 4]) = v;
    }
    __syncthreads();

    // ---- fused output projection: out = O @ Wo^T + bo (hi/lo exact A) ----
    float acco[4][4] = {};
    const int n0o = wn * 32;
    #pragma unroll
    for (int ks = 0; ks < 16; ks++) {
        int k0 = ks * 8;
        uint32_t ah[4], al[4];
        load_split(smf,
            O_OFF + (m0 + r) * OSTR + k0 + c,     O_OFF + (m0 + r + 8) * OSTR + k0 + c,
            O_OFF + (m0 + r) * OSTR + k0 + c + 4, O_OFF + (m0 + r + 8) * OSTR + k0 + c + 4,
            ah, al);
        #pragma unroll
        for (int nt = 0; nt < 4; nt++) {
            uint32_t b[2];
            b[0] = smu[K_OFF + (n0o + nt * 8 + r) * QSTR + k0 + c];
            b[1] = smu[K_OFF + (n0o + nt * 8 + r) * QSTR + k0 + c + 4];
            mma_tf32(acco[nt], ah, b);
            mma_tf32(acco[nt], al, b);
        }
    }
    #pragma unroll
    for (int nt = 0; nt < 4; nt++) {
        int gc = n0o + nt * 8 + c * 2;
        float bx = bo[gc], by = bo[gc + 1];
        #pragma unroll
        for (int half = 0; half < 2; half++) {
            size_t row = qrow0 + m0 + r + half * 8;
            float2 v = make_float2(acco[nt][half * 2] + bx, acco[nt][half * 2 + 1] + by);
            *reinterpret_cast<float2*>(&out[row * CZ + gc]) = v;
        }
    }
}

// ---------------- launch ----------------
extern "C" void kernel_launch(void* const* d_in, const int* in_sizes, int n_in,
                              void* d_out, int out_size)
{
    const float* z   = (const float*)d_in[0];
    const float* lnw = (const float*)d_in[1];
    const float* lnb = (const float*)d_in[2];
    const float* Wq  = (const float*)d_in[3];
    const float* Wk  = (const float*)d_in[4];
    const float* Wv  = (const float*)d_in[5];
    // d_in[6] = Wb : bias broadcasts along the key axis -> softmax-invariant -> unused
    const float* Wg  = (const float*)d_in[7];
    const float* bg  = (const float*)d_in[8];
    const float* Wo  = (const float*)d_in[9];
    const float* bo  = (const float*)d_in[10];
    float* out = (float*)d_out;
    (void)in_sizes; (void)n_in; (void)out_size;

    cudaFuncSetAttribute(proj_mma, cudaFuncAttributeMaxDynamicSharedMemorySize, PROJ_SMEM);
    cudaFuncSetAttribute(attn_mma_kernel, cudaFuncAttributeMaxDynamicSharedMemorySize, ATTN_SMEM_B);

    prep_w<<<448, 128>>>(Wq, Wk, Wv, Wg, Wo);
    proj_mma<<<NROWS / 64, 512, PROJ_SMEM>>>(z, lnw, lnb, bg);
    attn_mma_kernel<<<dim3(6, S_DIM), 512, ATTN_SMEM_B>>>(bo, out);
}